// round 1
// baseline (speedup 1.0000x reference)
#include <cuda_runtime.h>
#include <math.h>

#define Nn 30000
#define Ee 480000
#define Hh 256
#define Tt 4
#define Gg 64
#define Cc 10
#define STEPS 5
#define BN_EPS 1e-5f

#define WH_COLS (Tt * Hh)      // 1024
#define G3H (3 * Hh)           // 768

// ---------------- scratch (device globals; no runtime allocation) ----------------
__device__ float g_h[Nn * Hh];
__device__ float g_Wh[Nn * WH_COLS];     // layout [N][T*H]: row slice (src,etype) contiguous
__device__ float g_a[Nn * Hh];
__device__ float g_gi[Nn * G3H];
__device__ float g_gh[Nn * G3H];
__device__ float g_h2[Nn * Hh];
__device__ float g_gate[Nn];
__device__ float g_alpha[Nn];
__device__ float g_hg[Gg * Hh];
__device__ float g_colsum[Hh];
__device__ float g_colsq[Hh];
__device__ float g_scale[Hh];
__device__ float g_shift[Hh];
__device__ int   g_cnt[Nn];
__device__ int   g_rowptr[Nn + 1];
__device__ int   g_cursor[Nn];
__device__ int   g_eoff[Ee];
__device__ int   g_gcnt[Gg];
__device__ int   g_gstart[Gg + 1];

// ---------------- small utility kernels ----------------
__global__ void zero_f(float* p, int n) {
    int i = blockIdx.x * blockDim.x + threadIdx.x;
    if (i < n) p[i] = 0.0f;
}
__global__ void zero_i(int* p, int n) {
    int i = blockIdx.x * blockDim.x + threadIdx.x;
    if (i < n) p[i] = 0;
}
__global__ void copy_f4(const float4* __restrict__ src, float4* __restrict__ dst, int n4) {
    int i = blockIdx.x * blockDim.x + threadIdx.x;
    if (i < n4) dst[i] = src[i];
}

// ---------------- CSR construction ----------------
__global__ void hist_k(const int* __restrict__ dst, int* cnt) {
    int e = blockIdx.x * blockDim.x + threadIdx.x;
    if (e < Ee) atomicAdd(&cnt[dst[e]], 1);
}

__global__ void scan_k(const int* __restrict__ cnt, int* rowptr) {
    __shared__ int partial[1024];
    const int CH = (Nn + 1023) / 1024;  // 30
    int tid = threadIdx.x;
    int base = tid * CH;
    int s = 0;
#pragma unroll
    for (int i = 0; i < CH; i++) {
        int idx = base + i;
        if (idx < Nn) s += cnt[idx];
    }
    partial[tid] = s;
    __syncthreads();
    // Hillis-Steele inclusive scan
    for (int off = 1; off < 1024; off <<= 1) {
        int v = (tid >= off) ? partial[tid - off] : 0;
        __syncthreads();
        partial[tid] += v;
        __syncthreads();
    }
    int run = partial[tid] - s;  // exclusive prefix
    for (int i = 0; i < CH; i++) {
        int idx = base + i;
        if (idx < Nn) { rowptr[idx] = run; run += cnt[idx]; }
    }
    if (tid == 1023) rowptr[Nn] = partial[1023];
}

__global__ void copy_rowptr_k(const int* __restrict__ rowptr, int* cursor) {
    int i = blockIdx.x * blockDim.x + threadIdx.x;
    if (i < Nn) cursor[i] = rowptr[i];
}

__global__ void scatter_k(const int* __restrict__ src, const int* __restrict__ dst,
                          const int* __restrict__ etype, int* cursor, int* eoff) {
    int e = blockIdx.x * blockDim.x + threadIdx.x;
    if (e < Ee) {
        int pos = atomicAdd(&cursor[dst[e]], 1);
        eoff[pos] = src[e] * WH_COLS + etype[e] * Hh;
    }
}

// ---------------- GEMM: C[M,Ncols] = A[M,256] @ B[Ncols,256]^T + bias ----------------
// BM=128, BN=64, BK=16, 256 threads, 8x4 microtile.
__global__ __launch_bounds__(256) void gemm_nt(const float* __restrict__ A,
                                               const float* __restrict__ B,
                                               const float* __restrict__ bias,
                                               float* __restrict__ C,
                                               int M, int Ncols) {
    __shared__ float As[16][128];
    __shared__ float Bs[16][64];
    const int tid = threadIdx.x;
    const int tx = tid & 15;
    const int ty = tid >> 4;
    const int m0 = blockIdx.y * 128;
    const int n0 = blockIdx.x * 64;

    float acc[8][4];
#pragma unroll
    for (int i = 0; i < 8; i++)
#pragma unroll
        for (int j = 0; j < 4; j++) acc[i][j] = 0.0f;

    for (int k0 = 0; k0 < 256; k0 += 16) {
        // load A tile: 128x16 = 512 float4 (2 per thread), transpose into As
#pragma unroll
        for (int l = 0; l < 2; l++) {
            int idx = tid + l * 256;
            int row = idx >> 2;
            int kc = (idx & 3) * 4;
            float4 v = make_float4(0.f, 0.f, 0.f, 0.f);
            int gr = m0 + row;
            if (gr < M) v = *(const float4*)&A[gr * 256 + k0 + kc];
            As[kc + 0][row] = v.x;
            As[kc + 1][row] = v.y;
            As[kc + 2][row] = v.z;
            As[kc + 3][row] = v.w;
        }
        // load B tile: 64x16 = 256 float4 (1 per thread)
        {
            int row = tid >> 2;
            int kc = (tid & 3) * 4;
            float4 v = *(const float4*)&B[(n0 + row) * 256 + k0 + kc];
            Bs[kc + 0][row] = v.x;
            Bs[kc + 1][row] = v.y;
            Bs[kc + 2][row] = v.z;
            Bs[kc + 3][row] = v.w;
        }
        __syncthreads();
#pragma unroll
        for (int k = 0; k < 16; k++) {
            float a[8], b[4];
            *(float4*)&a[0] = *(float4*)&As[k][ty * 8];
            *(float4*)&a[4] = *(float4*)&As[k][ty * 8 + 4];
            *(float4*)&b[0] = *(float4*)&Bs[k][tx * 4];
#pragma unroll
            for (int i = 0; i < 8; i++)
#pragma unroll
                for (int j = 0; j < 4; j++) acc[i][j] += a[i] * b[j];
        }
        __syncthreads();
    }

    float bv[4];
#pragma unroll
    for (int j = 0; j < 4; j++) bv[j] = bias[n0 + tx * 4 + j];

#pragma unroll
    for (int i = 0; i < 8; i++) {
        int gr = m0 + ty * 8 + i;
        if (gr < M) {
            float4 o;
            o.x = acc[i][0] + bv[0];
            o.y = acc[i][1] + bv[1];
            o.z = acc[i][2] + bv[2];
            o.w = acc[i][3] + bv[3];
            *(float4*)&C[gr * Ncols + n0 + tx * 4] = o;
        }
    }
}

// ---------------- edge aggregation: a[d] = sum over in-edges of Wh[etype,src] ----------------
__global__ void aggregate_k(const float* __restrict__ Wh, const int* __restrict__ rowptr,
                            const int* __restrict__ eoff, float* __restrict__ a) {
    int d = blockIdx.x;
    int lane = threadIdx.x;  // 64 threads, 4 floats each
    int s = rowptr[d];
    int e = rowptr[d + 1];
    float4 acc = make_float4(0.f, 0.f, 0.f, 0.f);
    for (int i = s; i < e; i++) {
        int off = __ldg(&eoff[i]);
        float4 v = __ldg((const float4*)&Wh[off] + lane);
        acc.x += v.x; acc.y += v.y; acc.z += v.z; acc.w += v.w;
    }
    ((float4*)&a[d * Hh])[lane] = acc;
}

// ---------------- GRU elementwise ----------------
__global__ void gru_k(const float* __restrict__ gi, const float* __restrict__ gh,
                      float* __restrict__ h) {
    int i = blockIdx.x * blockDim.x + threadIdx.x;
    if (i >= Nn * Hh) return;
    int n = i >> 8;
    int c = i & 255;
    const float* gin = gi + n * G3H;
    const float* ghn = gh + n * G3H;
    float r = 1.0f / (1.0f + expf(-(gin[c] + ghn[c])));
    float z = 1.0f / (1.0f + expf(-(gin[256 + c] + ghn[256 + c])));
    float nn = tanhf(gin[512 + c] + r * ghn[512 + c]);
    float hv = h[i];
    h[i] = (1.0f - z) * nn + z * hv;
}

// ---------------- ELU + batchnorm stats ----------------
__global__ void elu_stats_k(const float* __restrict__ h, float* __restrict__ h2,
                            float* colsum, float* colsq) {
    int c = threadIdx.x;  // 256
    int rows_per_block = (Nn + gridDim.x - 1) / gridDim.x;
    int r0 = blockIdx.x * rows_per_block;
    int r1 = min(Nn, r0 + rows_per_block);
    float s = 0.f, q = 0.f;
    for (int r = r0; r < r1; r++) {
        float x = h[r * Hh + c];
        float e = x > 0.f ? x : expm1f(x);
        h2[r * Hh + c] = e;
        s += e;
        q += e * e;
    }
    atomicAdd(&colsum[c], s);
    atomicAdd(&colsq[c], q);
}

__global__ void bn_final_k(const float* __restrict__ colsum, const float* __restrict__ colsq,
                           const float* __restrict__ gamma, const float* __restrict__ beta,
                           float* scale, float* shift) {
    int c = threadIdx.x;
    float mu = colsum[c] * (1.0f / Nn);
    float var = colsq[c] * (1.0f / Nn) - mu * mu;
    float k = rsqrtf(var + BN_EPS) * gamma[c];
    scale[c] = k;
    shift[c] = beta[c] - mu * k;
}

__global__ void bn_apply_k(float* __restrict__ h2, const float* __restrict__ scale,
                           const float* __restrict__ shift) {
    int i = blockIdx.x * blockDim.x + threadIdx.x;
    if (i >= Nn * Hh) return;
    int c = i & 255;
    h2[i] = h2[i] * scale[c] + shift[c];
}

// ---------------- gate scores ----------------
__global__ void gate_k(const float* __restrict__ h2, const float* __restrict__ gw,
                       const float* __restrict__ gb, float* __restrict__ gate) {
    int warp = threadIdx.x >> 5;
    int lane = threadIdx.x & 31;
    int n = blockIdx.x * 8 + warp;
    if (n >= Nn) return;
    float s = 0.f;
#pragma unroll
    for (int c = lane; c < Hh; c += 32) s += h2[n * Hh + c] * gw[c];
#pragma unroll
    for (int o = 16; o > 0; o >>= 1) s += __shfl_xor_sync(0xffffffffu, s, o);
    if (lane == 0) gate[n] = s + gb[0];
}

// ---------------- per-graph ranges ----------------
__global__ void ghist_k(const int* __restrict__ n2g, int* gcnt) {
    int i = blockIdx.x * blockDim.x + threadIdx.x;
    if (i < Nn) atomicAdd(&gcnt[n2g[i]], 1);
}
__global__ void gscan_k(const int* __restrict__ gcnt, int* gstart) {
    if (threadIdx.x == 0 && blockIdx.x == 0) {
        int r = 0;
        for (int g = 0; g < Gg; g++) { gstart[g] = r; r += gcnt[g]; }
        gstart[Gg] = r;
    }
}

// ---------------- fused segment softmax + weighted pooling ----------------
__global__ void pool_k(const float* __restrict__ h2, const float* __restrict__ gate,
                       const int* __restrict__ gstart, float* __restrict__ alpha,
                       float* __restrict__ hg) {
    int g = blockIdx.x;
    int t = threadIdx.x;  // 256
    __shared__ float red[256];
    int s = gstart[g];
    int e = gstart[g + 1];
    if (e == s) { hg[g * Hh + t] = 0.0f; return; }
    // pass 1: max
    float mx = -3.402823e38f;
    for (int n = s + t; n < e; n += 256) mx = fmaxf(mx, gate[n]);
    red[t] = mx;
    __syncthreads();
    for (int o = 128; o > 0; o >>= 1) {
        if (t < o) red[t] = fmaxf(red[t], red[t + o]);
        __syncthreads();
    }
    mx = red[0];
    __syncthreads();
    // pass 2: exp + sum
    float sm = 0.f;
    for (int n = s + t; n < e; n += 256) {
        float ee = expf(gate[n] - mx);
        alpha[n] = ee;
        sm += ee;
    }
    red[t] = sm;
    __syncthreads();
    for (int o = 128; o > 0; o >>= 1) {
        if (t < o) red[t] += red[t + o];
        __syncthreads();
    }
    float inv = 1.0f / red[0];
    __syncthreads();
    // pass 3: weighted column sum (thread t owns column t)
    float acc0 = 0.f, acc1 = 0.f, acc2 = 0.f, acc3 = 0.f;
    int n = s;
    for (; n + 3 < e; n += 4) {
        acc0 += alpha[n + 0] * h2[(n + 0) * Hh + t];
        acc1 += alpha[n + 1] * h2[(n + 1) * Hh + t];
        acc2 += alpha[n + 2] * h2[(n + 2) * Hh + t];
        acc3 += alpha[n + 3] * h2[(n + 3) * Hh + t];
    }
    for (; n < e; n++) acc0 += alpha[n] * h2[n * Hh + t];
    hg[g * Hh + t] = (acc0 + acc1 + acc2 + acc3) * inv;
}

// ---------------- classifier MLP ----------------
__global__ void mlp_k(const float* __restrict__ hg, const float* __restrict__ W1,
                      const float* __restrict__ b1, const float* __restrict__ W2,
                      const float* __restrict__ b2, float* __restrict__ out) {
    int g = blockIdx.x;
    int t = threadIdx.x;  // 128
    __shared__ float sh[256];
    __shared__ float sx[128];
    sh[t] = hg[g * Hh + t];
    sh[t + 128] = hg[g * Hh + t + 128];
    __syncthreads();
    float s = b1[t];
#pragma unroll 8
    for (int j = 0; j < 256; j++) s += sh[j] * W1[t * 256 + j];
    sx[t] = fmaxf(s, 0.f);
    __syncthreads();
    if (t < Cc) {
        float o = b2[t];
#pragma unroll 8
        for (int j = 0; j < 128; j++) o += sx[j] * W2[t * 128 + j];
        out[g * Cc + t] = o;
    }
}

// ---------------- launcher ----------------
extern "C" void kernel_launch(void* const* d_in, const int* in_sizes, int n_in,
                              void* d_out, int out_size) {
    const float* feat   = (const float*)d_in[0];
    const int*   src    = (const int*)d_in[1];
    const int*   dst    = (const int*)d_in[2];
    const int*   etype  = (const int*)d_in[3];
    const int*   n2g    = (const int*)d_in[4];
    const float* W_msg  = (const float*)d_in[5];   // [T,H,H] -> view [1024,256]
    const float* b_msg  = (const float*)d_in[6];   // [T,H]   -> view [1024]
    const float* w_ih   = (const float*)d_in[7];   // [768,256]
    const float* w_hh   = (const float*)d_in[8];   // [768,256]
    const float* b_ih   = (const float*)d_in[9];
    const float* b_hh   = (const float*)d_in[10];
    const float* bn_g   = (const float*)d_in[11];
    const float* bn_b   = (const float*)d_in[12];
    const float* gate_w = (const float*)d_in[13];
    const float* gate_b = (const float*)d_in[14];
    const float* W1     = (const float*)d_in[15];
    const float* b1     = (const float*)d_in[16];
    const float* W2     = (const float*)d_in[17];
    const float* b2     = (const float*)d_in[18];
    float* out = (float*)d_out;

    float *h, *Wh, *a, *gi, *gh, *h2, *gate, *alpha, *hg, *colsum, *colsq, *scale, *shift;
    int *cnt, *rowptr, *cursor, *eoff, *gcnt, *gstart;
    cudaGetSymbolAddress((void**)&h, g_h);
    cudaGetSymbolAddress((void**)&Wh, g_Wh);
    cudaGetSymbolAddress((void**)&a, g_a);
    cudaGetSymbolAddress((void**)&gi, g_gi);
    cudaGetSymbolAddress((void**)&gh, g_gh);
    cudaGetSymbolAddress((void**)&h2, g_h2);
    cudaGetSymbolAddress((void**)&gate, g_gate);
    cudaGetSymbolAddress((void**)&alpha, g_alpha);
    cudaGetSymbolAddress((void**)&hg, g_hg);
    cudaGetSymbolAddress((void**)&colsum, g_colsum);
    cudaGetSymbolAddress((void**)&colsq, g_colsq);
    cudaGetSymbolAddress((void**)&scale, g_scale);
    cudaGetSymbolAddress((void**)&shift, g_shift);
    cudaGetSymbolAddress((void**)&cnt, g_cnt);
    cudaGetSymbolAddress((void**)&rowptr, g_rowptr);
    cudaGetSymbolAddress((void**)&cursor, g_cursor);
    cudaGetSymbolAddress((void**)&eoff, g_eoff);
    cudaGetSymbolAddress((void**)&gcnt, g_gcnt);
    cudaGetSymbolAddress((void**)&gstart, g_gstart);

    // h = feat
    copy_f4<<<(Nn * Hh / 4 + 255) / 256, 256>>>((const float4*)feat, (float4*)h, Nn * Hh / 4);

    // CSR by dst (once per launch)
    zero_i<<<(Nn + 255) / 256, 256>>>(cnt, Nn);
    hist_k<<<(Ee + 255) / 256, 256>>>(dst, cnt);
    scan_k<<<1, 1024>>>(cnt, rowptr);
    copy_rowptr_k<<<(Nn + 255) / 256, 256>>>(rowptr, cursor);
    scatter_k<<<(Ee + 255) / 256, 256>>>(src, dst, etype, cursor, eoff);

    dim3 gridWh(WH_COLS / 64, (Nn + 127) / 128);
    dim3 gridG(G3H / 64, (Nn + 127) / 128);

    for (int step = 0; step < STEPS; step++) {
        gemm_nt<<<gridWh, 256>>>(h, W_msg, b_msg, Wh, Nn, WH_COLS);
        aggregate_k<<<Nn, 64>>>(Wh, rowptr, eoff, a);
        gemm_nt<<<gridG, 256>>>(h, w_hh, b_hh, gh, Nn, G3H);
        gemm_nt<<<gridG, 256>>>(a, w_ih, b_ih, gi, Nn, G3H);
        gru_k<<<(Nn * Hh + 255) / 256, 256>>>(gi, gh, h);
    }

    // ELU + BN (training-mode batch stats)
    zero_f<<<2, 256>>>(colsum, Hh);  // covers colsum; next covers colsq
    zero_f<<<2, 256>>>(colsq, Hh);
    elu_stats_k<<<120, 256>>>(h, h2, colsum, colsq);
    bn_final_k<<<1, 256>>>(colsum, colsq, bn_g, bn_b, scale, shift);
    bn_apply_k<<<(Nn * Hh + 255) / 256, 256>>>(h2, scale, shift);

    // gate + per-graph softmax pooling
    gate_k<<<(Nn + 7) / 8, 256>>>(h2, gate_w, gate_b, gate);
    zero_i<<<1, 64>>>(gcnt, Gg);
    ghist_k<<<(Nn + 255) / 256, 256>>>(n2g, gcnt);
    gscan_k<<<1, 32>>>(gcnt, gstart);
    pool_k<<<Gg, 256>>>(h2, gate, gstart, alpha, hg);

    // classifier
    mlp_k<<<Gg, 128>>>(hg, W1, b1, W2, b2, out);
}

// round 3
// speedup vs baseline: 1.8959x; 1.8959x over previous
#include <cuda_runtime.h>
#include <cuda_bf16.h>
#include <stdint.h>
#include <math.h>

#define Nn 30000
#define Ee 480000
#define Hh 256
#define Tt 4
#define Gg 64
#define Cc 10
#define STEPS 5
#define BN_EPS 1e-5f

#define WH_COLS (Tt * Hh)      // 1024
#define G3H (3 * Hh)           // 768

// ---------------- scratch (device globals; no runtime allocation) ----------------
__device__ float g_h[Nn * Hh];
__device__ float g_Wh[Nn * WH_COLS];
__device__ float g_gi[Nn * G3H];
__device__ float g_gh[Nn * G3H];
__device__ float g_h2[Nn * Hh];
__device__ float g_gate[Nn];
__device__ float g_alpha[Nn];
__device__ float g_hg[Gg * Hh];
__device__ float g_colsum[Hh];
__device__ float g_colsq[Hh];
__device__ float g_scale[Hh];
__device__ float g_shift[Hh];
__device__ int   g_cnt[Nn];
__device__ int   g_rowptr[Nn + 1];
__device__ int   g_cursor[Nn];
__device__ int   g_eoff[Ee];
__device__ int   g_gcnt[Gg];
__device__ int   g_gstart[Gg + 1];
// bf16 hi/lo split operands for tensor-core GEMMs
__device__ __nv_bfloat16 g_h_hi[Nn * Hh];
__device__ __nv_bfloat16 g_h_lo[Nn * Hh];
__device__ __nv_bfloat16 g_a_hi[Nn * Hh];
__device__ __nv_bfloat16 g_a_lo[Nn * Hh];
__device__ __nv_bfloat16 g_Wm_hi[WH_COLS * Hh];
__device__ __nv_bfloat16 g_Wm_lo[WH_COLS * Hh];
__device__ __nv_bfloat16 g_wih_hi[G3H * Hh];
__device__ __nv_bfloat16 g_wih_lo[G3H * Hh];
__device__ __nv_bfloat16 g_whh_hi[G3H * Hh];
__device__ __nv_bfloat16 g_whh_lo[G3H * Hh];

// ---------------- mma.sync helpers (baseline ISA, runs on HMMA pipe) ----------------
__device__ __forceinline__ uint32_t smem_u32(const void* p) {
    uint32_t a;
    asm("{ .reg .u64 t; cvta.to.shared.u64 t, %1; cvt.u32.u64 %0, t; }" : "=r"(a) : "l"(p));
    return a;
}
__device__ __forceinline__ void ldm_x4(uint32_t& r0, uint32_t& r1, uint32_t& r2, uint32_t& r3,
                                       uint32_t addr) {
    asm volatile("ldmatrix.sync.aligned.m8n8.x4.shared.b16 {%0,%1,%2,%3}, [%4];"
                 : "=r"(r0), "=r"(r1), "=r"(r2), "=r"(r3) : "r"(addr));
}
__device__ __forceinline__ void mma_bf16(float* d, const uint32_t* a, const uint32_t* b) {
    asm volatile(
        "mma.sync.aligned.m16n8k16.row.col.f32.bf16.bf16.f32 "
        "{%0,%1,%2,%3}, {%4,%5,%6,%7}, {%8,%9}, {%0,%1,%2,%3};"
        : "+f"(d[0]), "+f"(d[1]), "+f"(d[2]), "+f"(d[3])
        : "r"(a[0]), "r"(a[1]), "r"(a[2]), "r"(a[3]), "r"(b[0]), "r"(b[1]));
}

// ---------------- tensor-core GEMM via mma.sync ----------------
// C[M,Ncols] = (Ahi+Alo)[M,256] @ (Bhi+Blo)[Ncols,256]^T + bias
// fp32 emulation: C = Ahi*Bhi + Ahi*Blo + Alo*Bhi
// BM=128, BN=64, BK=32, 8 warps (4x2), warp tile 32x32.
#define SSTR 40  // smem row stride in bf16 elems (80 bytes; 16B-aligned for ldmatrix)

__global__ __launch_bounds__(256) void gemm_mma(
    const __nv_bfloat16* __restrict__ Ahi, const __nv_bfloat16* __restrict__ Alo,
    const __nv_bfloat16* __restrict__ Bhi, const __nv_bfloat16* __restrict__ Blo,
    const float* __restrict__ bias, float* __restrict__ C, int M, int Ncols) {
    __shared__ __nv_bfloat16 sAhi[128 * SSTR];
    __shared__ __nv_bfloat16 sAlo[128 * SSTR];
    __shared__ __nv_bfloat16 sBhi[64 * SSTR];
    __shared__ __nv_bfloat16 sBlo[64 * SSTR];

    const int tid = threadIdx.x;
    const int warp = tid >> 5;
    const int lane = tid & 31;
    const int wm = warp >> 1;   // 0..3 -> m offset wm*32
    const int wn = warp & 1;    // 0..1 -> n offset wn*32
    const int m0 = blockIdx.y * 128;
    const int n0 = blockIdx.x * 64;

    // global load mapping: each thread owns (row = tid>>2, k4 = tid&3) 16B chunk
    const int grow = tid >> 2;      // 0..63
    const int gk4 = (tid & 3) * 8;  // bf16 elem offset within BK
    const bool av0 = (m0 + grow) < M;
    const bool av1 = (m0 + grow + 64) < M;
    const uint4 z4 = make_uint4(0u, 0u, 0u, 0u);

    // ldmatrix per-lane smem offsets (bytes)
    const uint32_t aB_hi = smem_u32(sAhi), aB_lo = smem_u32(sAlo);
    const uint32_t bB_hi = smem_u32(sBhi), bB_lo = smem_u32(sBlo);
    const int alr = lane & 15, alh = lane >> 4;
    uint32_t aoff[2];
#pragma unroll
    for (int tm = 0; tm < 2; tm++)
        aoff[tm] = (uint32_t)((wm * 32 + tm * 16 + alr) * (SSTR * 2) + alh * 16);
    const int bnr = (lane & 7) + ((lane >> 4) & 1) * 8;
    const int bkh = ((lane >> 3) & 1) * 16;
    uint32_t boff[2];
#pragma unroll
    for (int bt = 0; bt < 2; bt++)
        boff[bt] = (uint32_t)((wn * 32 + bt * 16 + bnr) * (SSTR * 2) + bkh);

    float acc[2][4][4];
#pragma unroll
    for (int i = 0; i < 2; i++)
#pragma unroll
        for (int j = 0; j < 4; j++)
#pragma unroll
            for (int q = 0; q < 4; q++) acc[i][j][q] = 0.0f;

    for (int k0 = 0; k0 < 256; k0 += 32) {
        __syncthreads();
        // A tiles (128x32 hi+lo), rows grow and grow+64
        {
            const __nv_bfloat16* pa = Ahi + (size_t)(m0 + grow) * 256 + k0 + gk4;
            const __nv_bfloat16* pl = Alo + (size_t)(m0 + grow) * 256 + k0 + gk4;
            *(uint4*)&sAhi[grow * SSTR + gk4] = av0 ? *(const uint4*)pa : z4;
            *(uint4*)&sAlo[grow * SSTR + gk4] = av0 ? *(const uint4*)pl : z4;
            *(uint4*)&sAhi[(grow + 64) * SSTR + gk4] = av1 ? *(const uint4*)(pa + 64 * 256) : z4;
            *(uint4*)&sAlo[(grow + 64) * SSTR + gk4] = av1 ? *(const uint4*)(pl + 64 * 256) : z4;
        }
        // B tiles (64x32 hi+lo)
        {
            const __nv_bfloat16* pb = Bhi + (size_t)(n0 + grow) * 256 + k0 + gk4;
            const __nv_bfloat16* pq = Blo + (size_t)(n0 + grow) * 256 + k0 + gk4;
            *(uint4*)&sBhi[grow * SSTR + gk4] = *(const uint4*)pb;
            *(uint4*)&sBlo[grow * SSTR + gk4] = *(const uint4*)pq;
        }
        __syncthreads();

#pragma unroll
        for (int kk = 0; kk < 2; kk++) {
            uint32_t ah[2][4], al[2][4], bh[2][4], bl[2][4];
#pragma unroll
            for (int tm = 0; tm < 2; tm++) {
                ldm_x4(ah[tm][0], ah[tm][1], ah[tm][2], ah[tm][3], aB_hi + aoff[tm] + kk * 32);
                ldm_x4(al[tm][0], al[tm][1], al[tm][2], al[tm][3], aB_lo + aoff[tm] + kk * 32);
            }
#pragma unroll
            for (int bt = 0; bt < 2; bt++) {
                ldm_x4(bh[bt][0], bh[bt][1], bh[bt][2], bh[bt][3], bB_hi + boff[bt] + kk * 32);
                ldm_x4(bl[bt][0], bl[bt][1], bl[bt][2], bl[bt][3], bB_lo + boff[bt] + kk * 32);
            }
#pragma unroll
            for (int tm = 0; tm < 2; tm++) {
#pragma unroll
                for (int tn = 0; tn < 4; tn++) {
                    const uint32_t* bph = &bh[tn >> 1][(tn & 1) * 2];
                    const uint32_t* bpl = &bl[tn >> 1][(tn & 1) * 2];
                    mma_bf16(acc[tm][tn], ah[tm], bph);
                    mma_bf16(acc[tm][tn], ah[tm], bpl);
                    mma_bf16(acc[tm][tn], al[tm], bph);
                }
            }
        }
    }

    // epilogue
    const int erow = (lane >> 2);
    const int ecol = (lane & 3) * 2;
#pragma unroll
    for (int tm = 0; tm < 2; tm++) {
#pragma unroll
        for (int tn = 0; tn < 4; tn++) {
            int col = n0 + wn * 32 + tn * 8 + ecol;
            float2 bv = *(const float2*)&bias[col];
            int r0 = m0 + wm * 32 + tm * 16 + erow;
            if (r0 < M) {
                float2 o;
                o.x = acc[tm][tn][0] + bv.x;
                o.y = acc[tm][tn][1] + bv.y;
                *(float2*)&C[(size_t)r0 * Ncols + col] = o;
            }
            int r1 = r0 + 8;
            if (r1 < M) {
                float2 o;
                o.x = acc[tm][tn][2] + bv.x;
                o.y = acc[tm][tn][3] + bv.y;
                *(float2*)&C[(size_t)r1 * Ncols + col] = o;
            }
        }
    }
}

// ---------------- fp32 -> bf16 hi/lo split ----------------
__global__ void split_k(const float* __restrict__ x, __nv_bfloat16* __restrict__ hi,
                        __nv_bfloat16* __restrict__ lo, int n) {
    int i = blockIdx.x * blockDim.x + threadIdx.x;
    if (i < n) {
        float v = x[i];
        __nv_bfloat16 h = __float2bfloat16(v);
        hi[i] = h;
        lo[i] = __float2bfloat16(v - __bfloat162float(h));
    }
}
__global__ void init_h_k(const float* __restrict__ feat, float* __restrict__ h,
                         __nv_bfloat16* __restrict__ hhi, __nv_bfloat16* __restrict__ hlo) {
    int i = blockIdx.x * blockDim.x + threadIdx.x;
    if (i < Nn * Hh) {
        float v = feat[i];
        h[i] = v;
        __nv_bfloat16 hb = __float2bfloat16(v);
        hhi[i] = hb;
        hlo[i] = __float2bfloat16(v - __bfloat162float(hb));
    }
}

// ---------------- CSR construction ----------------
__global__ void zero_f(float* p, int n) {
    int i = blockIdx.x * blockDim.x + threadIdx.x;
    if (i < n) p[i] = 0.0f;
}
__global__ void zero_i(int* p, int n) {
    int i = blockIdx.x * blockDim.x + threadIdx.x;
    if (i < n) p[i] = 0;
}
__global__ void hist_k(const int* __restrict__ dst, int* cnt) {
    int e = blockIdx.x * blockDim.x + threadIdx.x;
    if (e < Ee) atomicAdd(&cnt[dst[e]], 1);
}
__global__ void scan_k(const int* __restrict__ cnt, int* rowptr) {
    __shared__ int partial[1024];
    const int CH = (Nn + 1023) / 1024;
    int tid = threadIdx.x;
    int base = tid * CH;
    int s = 0;
#pragma unroll
    for (int i = 0; i < CH; i++) {
        int idx = base + i;
        if (idx < Nn) s += cnt[idx];
    }
    partial[tid] = s;
    __syncthreads();
    for (int off = 1; off < 1024; off <<= 1) {
        int v = (tid >= off) ? partial[tid - off] : 0;
        __syncthreads();
        partial[tid] += v;
        __syncthreads();
    }
    int run = partial[tid] - s;
    for (int i = 0; i < CH; i++) {
        int idx = base + i;
        if (idx < Nn) { rowptr[idx] = run; run += cnt[idx]; }
    }
    if (tid == 1023) rowptr[Nn] = partial[1023];
}
__global__ void copy_rowptr_k(const int* __restrict__ rowptr, int* cursor) {
    int i = blockIdx.x * blockDim.x + threadIdx.x;
    if (i < Nn) cursor[i] = rowptr[i];
}
__global__ void scatter_k(const int* __restrict__ src, const int* __restrict__ dst,
                          const int* __restrict__ etype, int* cursor, int* eoff) {
    int e = blockIdx.x * blockDim.x + threadIdx.x;
    if (e < Ee) {
        int pos = atomicAdd(&cursor[dst[e]], 1);
        eoff[pos] = src[e] * WH_COLS + etype[e] * Hh;
    }
}

// ---------------- edge aggregation: a[d] = sum Wh[etype,src]; emits bf16 hi/lo ----------------
__global__ void aggregate_k(const float* __restrict__ Wh, const int* __restrict__ rowptr,
                            const int* __restrict__ eoff,
                            __nv_bfloat16* __restrict__ ahi, __nv_bfloat16* __restrict__ alo) {
    int d = blockIdx.x;
    int lane = threadIdx.x;  // 64 threads, 4 floats each
    int s = rowptr[d];
    int e = rowptr[d + 1];
    float4 acc = make_float4(0.f, 0.f, 0.f, 0.f);
    for (int i = s; i < e; i++) {
        int off = __ldg(&eoff[i]);
        float4 v = __ldg((const float4*)&Wh[off] + lane);
        acc.x += v.x; acc.y += v.y; acc.z += v.z; acc.w += v.w;
    }
    float vals[4] = {acc.x, acc.y, acc.z, acc.w};
    __nv_bfloat16 hb[4], lb[4];
#pragma unroll
    for (int q = 0; q < 4; q++) {
        hb[q] = __float2bfloat16(vals[q]);
        lb[q] = __float2bfloat16(vals[q] - __bfloat162float(hb[q]));
    }
    *(uint2*)&ahi[(size_t)d * Hh + lane * 4] = *(uint2*)hb;
    *(uint2*)&alo[(size_t)d * Hh + lane * 4] = *(uint2*)lb;
}

// ---------------- GRU elementwise (fused h hi/lo split) ----------------
__global__ void gru_k(const float* __restrict__ gi, const float* __restrict__ gh,
                      float* __restrict__ h,
                      __nv_bfloat16* __restrict__ hhi, __nv_bfloat16* __restrict__ hlo) {
    int i = blockIdx.x * blockDim.x + threadIdx.x;
    if (i >= Nn * Hh) return;
    int n = i >> 8;
    int c = i & 255;
    const float* gin = gi + (size_t)n * G3H;
    const float* ghn = gh + (size_t)n * G3H;
    float r = 1.0f / (1.0f + expf(-(gin[c] + ghn[c])));
    float z = 1.0f / (1.0f + expf(-(gin[256 + c] + ghn[256 + c])));
    float nn = tanhf(gin[512 + c] + r * ghn[512 + c]);
    float hv = h[i];
    float o = (1.0f - z) * nn + z * hv;
    h[i] = o;
    __nv_bfloat16 hb = __float2bfloat16(o);
    hhi[i] = hb;
    hlo[i] = __float2bfloat16(o - __bfloat162float(hb));
}

// ---------------- ELU + batchnorm ----------------
__global__ void elu_stats_k(const float* __restrict__ h, float* __restrict__ h2,
                            float* colsum, float* colsq) {
    int c = threadIdx.x;
    int rows_per_block = (Nn + gridDim.x - 1) / gridDim.x;
    int r0 = blockIdx.x * rows_per_block;
    int r1 = min(Nn, r0 + rows_per_block);
    float s = 0.f, q = 0.f;
    for (int r = r0; r < r1; r++) {
        float x = h[(size_t)r * Hh + c];
        float e = x > 0.f ? x : expm1f(x);
        h2[(size_t)r * Hh + c] = e;
        s += e;
        q += e * e;
    }
    atomicAdd(&colsum[c], s);
    atomicAdd(&colsq[c], q);
}
__global__ void bn_final_k(const float* __restrict__ colsum, const float* __restrict__ colsq,
                           const float* __restrict__ gamma, const float* __restrict__ beta,
                           float* scale, float* shift) {
    int c = threadIdx.x;
    float mu = colsum[c] * (1.0f / Nn);
    float var = colsq[c] * (1.0f / Nn) - mu * mu;
    float k = rsqrtf(var + BN_EPS) * gamma[c];
    scale[c] = k;
    shift[c] = beta[c] - mu * k;
}
__global__ void bn_apply_k(float* __restrict__ h2, const float* __restrict__ scale,
                           const float* __restrict__ shift) {
    int i = blockIdx.x * blockDim.x + threadIdx.x;
    if (i >= Nn * Hh) return;
    int c = i & 255;
    h2[i] = h2[i] * scale[c] + shift[c];
}

// ---------------- gate + pooling + classifier ----------------
__global__ void gate_k(const float* __restrict__ h2, const float* __restrict__ gw,
                       const float* __restrict__ gb, float* __restrict__ gate) {
    int warp = threadIdx.x >> 5;
    int lane = threadIdx.x & 31;
    int n = blockIdx.x * 8 + warp;
    if (n >= Nn) return;
    float s = 0.f;
#pragma unroll
    for (int c = lane; c < Hh; c += 32) s += h2[(size_t)n * Hh + c] * gw[c];
#pragma unroll
    for (int o = 16; o > 0; o >>= 1) s += __shfl_xor_sync(0xffffffffu, s, o);
    if (lane == 0) gate[n] = s + gb[0];
}
__global__ void ghist_k(const int* __restrict__ n2g, int* gcnt) {
    int i = blockIdx.x * blockDim.x + threadIdx.x;
    if (i < Nn) atomicAdd(&gcnt[n2g[i]], 1);
}
__global__ void gscan_k(const int* __restrict__ gcnt, int* gstart) {
    if (threadIdx.x == 0 && blockIdx.x == 0) {
        int r = 0;
        for (int g = 0; g < Gg; g++) { gstart[g] = r; r += gcnt[g]; }
        gstart[Gg] = r;
    }
}
__global__ void pool_k(const float* __restrict__ h2, const float* __restrict__ gate,
                       const int* __restrict__ gstart, float* __restrict__ alpha,
                       float* __restrict__ hg) {
    int g = blockIdx.x;
    int t = threadIdx.x;
    __shared__ float red[256];
    int s = gstart[g];
    int e = gstart[g + 1];
    if (e == s) { hg[g * Hh + t] = 0.0f; return; }
    float mx = -3.402823e38f;
    for (int n = s + t; n < e; n += 256) mx = fmaxf(mx, gate[n]);
    red[t] = mx;
    __syncthreads();
    for (int o = 128; o > 0; o >>= 1) {
        if (t < o) red[t] = fmaxf(red[t], red[t + o]);
        __syncthreads();
    }
    mx = red[0];
    __syncthreads();
    float sm = 0.f;
    for (int n = s + t; n < e; n += 256) {
        float ee = expf(gate[n] - mx);
        alpha[n] = ee;
        sm += ee;
    }
    red[t] = sm;
    __syncthreads();
    for (int o = 128; o > 0; o >>= 1) {
        if (t < o) red[t] += red[t + o];
        __syncthreads();
    }
    float inv = 1.0f / red[0];
    __syncthreads();
    float acc0 = 0.f, acc1 = 0.f, acc2 = 0.f, acc3 = 0.f;
    int n = s;
    for (; n + 3 < e; n += 4) {
        acc0 += alpha[n + 0] * h2[(size_t)(n + 0) * Hh + t];
        acc1 += alpha[n + 1] * h2[(size_t)(n + 1) * Hh + t];
        acc2 += alpha[n + 2] * h2[(size_t)(n + 2) * Hh + t];
        acc3 += alpha[n + 3] * h2[(size_t)(n + 3) * Hh + t];
    }
    for (; n < e; n++) acc0 += alpha[n] * h2[(size_t)n * Hh + t];
    hg[g * Hh + t] = (acc0 + acc1 + acc2 + acc3) * inv;
}
__global__ void mlp_k(const float* __restrict__ hg, const float* __restrict__ W1,
                      const float* __restrict__ b1, const float* __restrict__ W2,
                      const float* __restrict__ b2, float* __restrict__ out) {
    int g = blockIdx.x;
    int t = threadIdx.x;
    __shared__ float sh[256];
    __shared__ float sx[128];
    sh[t] = hg[g * Hh + t];
    sh[t + 128] = hg[g * Hh + t + 128];
    __syncthreads();
    float s = b1[t];
#pragma unroll 8
    for (int j = 0; j < 256; j++) s += sh[j] * W1[t * 256 + j];
    sx[t] = fmaxf(s, 0.f);
    __syncthreads();
    if (t < Cc) {
        float o = b2[t];
#pragma unroll 8
        for (int j = 0; j < 128; j++) o += sx[j] * W2[t * 128 + j];
        out[g * Cc + t] = o;
    }
}

// ---------------- launcher ----------------
extern "C" void kernel_launch(void* const* d_in, const int* in_sizes, int n_in,
                              void* d_out, int out_size) {
    const float* feat   = (const float*)d_in[0];
    const int*   src    = (const int*)d_in[1];
    const int*   dst    = (const int*)d_in[2];
    const int*   etype  = (const int*)d_in[3];
    const int*   n2g    = (const int*)d_in[4];
    const float* W_msg  = (const float*)d_in[5];
    const float* b_msg  = (const float*)d_in[6];
    const float* w_ih   = (const float*)d_in[7];
    const float* w_hh   = (const float*)d_in[8];
    const float* b_ih   = (const float*)d_in[9];
    const float* b_hh   = (const float*)d_in[10];
    const float* bn_g   = (const float*)d_in[11];
    const float* bn_b   = (const float*)d_in[12];
    const float* gate_w = (const float*)d_in[13];
    const float* gate_b = (const float*)d_in[14];
    const float* W1     = (const float*)d_in[15];
    const float* b1     = (const float*)d_in[16];
    const float* W2     = (const float*)d_in[17];
    const float* b2     = (const float*)d_in[18];
    float* out = (float*)d_out;

    float *h, *Wh, *gi, *gh, *h2, *gate, *alpha, *hg, *colsum, *colsq, *scale, *shift;
    int *cnt, *rowptr, *cursor, *eoff, *gcnt, *gstart;
    __nv_bfloat16 *h_hi, *h_lo, *a_hi, *a_lo, *Wm_hi, *Wm_lo, *wih_hi, *wih_lo, *whh_hi, *whh_lo;
    cudaGetSymbolAddress((void**)&h, g_h);
    cudaGetSymbolAddress((void**)&Wh, g_Wh);
    cudaGetSymbolAddress((void**)&gi, g_gi);
    cudaGetSymbolAddress((void**)&gh, g_gh);
    cudaGetSymbolAddress((void**)&h2, g_h2);
    cudaGetSymbolAddress((void**)&gate, g_gate);
    cudaGetSymbolAddress((void**)&alpha, g_alpha);
    cudaGetSymbolAddress((void**)&hg, g_hg);
    cudaGetSymbolAddress((void**)&colsum, g_colsum);
    cudaGetSymbolAddress((void**)&colsq, g_colsq);
    cudaGetSymbolAddress((void**)&scale, g_scale);
    cudaGetSymbolAddress((void**)&shift, g_shift);
    cudaGetSymbolAddress((void**)&cnt, g_cnt);
    cudaGetSymbolAddress((void**)&rowptr, g_rowptr);
    cudaGetSymbolAddress((void**)&cursor, g_cursor);
    cudaGetSymbolAddress((void**)&eoff, g_eoff);
    cudaGetSymbolAddress((void**)&gcnt, g_gcnt);
    cudaGetSymbolAddress((void**)&gstart, g_gstart);
    cudaGetSymbolAddress((void**)&h_hi, g_h_hi);
    cudaGetSymbolAddress((void**)&h_lo, g_h_lo);
    cudaGetSymbolAddress((void**)&a_hi, g_a_hi);
    cudaGetSymbolAddress((void**)&a_lo, g_a_lo);
    cudaGetSymbolAddress((void**)&Wm_hi, g_Wm_hi);
    cudaGetSymbolAddress((void**)&Wm_lo, g_Wm_lo);
    cudaGetSymbolAddress((void**)&wih_hi, g_wih_hi);
    cudaGetSymbolAddress((void**)&wih_lo, g_wih_lo);
    cudaGetSymbolAddress((void**)&whh_hi, g_whh_hi);
    cudaGetSymbolAddress((void**)&whh_lo, g_whh_lo);

    // h = feat (+ hi/lo split); weight splits
    init_h_k<<<(Nn * Hh + 255) / 256, 256>>>(feat, h, h_hi, h_lo);
    split_k<<<(WH_COLS * Hh + 255) / 256, 256>>>(W_msg, Wm_hi, Wm_lo, WH_COLS * Hh);
    split_k<<<(G3H * Hh + 255) / 256, 256>>>(w_ih, wih_hi, wih_lo, G3H * Hh);
    split_k<<<(G3H * Hh + 255) / 256, 256>>>(w_hh, whh_hi, whh_lo, G3H * Hh);

    // CSR by dst
    zero_i<<<(Nn + 255) / 256, 256>>>(cnt, Nn);
    hist_k<<<(Ee + 255) / 256, 256>>>(dst, cnt);
    scan_k<<<1, 1024>>>(cnt, rowptr);
    copy_rowptr_k<<<(Nn + 255) / 256, 256>>>(rowptr, cursor);
    scatter_k<<<(Ee + 255) / 256, 256>>>(src, dst, etype, cursor, eoff);

    dim3 gridWh(WH_COLS / 64, (Nn + 127) / 128);
    dim3 gridG(G3H / 64, (Nn + 127) / 128);

    for (int step = 0; step < STEPS; step++) {
        gemm_mma<<<gridWh, 256>>>(h_hi, h_lo, Wm_hi, Wm_lo, b_msg, Wh, Nn, WH_COLS);
        aggregate_k<<<Nn, 64>>>(Wh, rowptr, eoff, a_hi, a_lo);
        gemm_mma<<<gridG, 256>>>(h_hi, h_lo, whh_hi, whh_lo, b_hh, gh, Nn, G3H);
        gemm_mma<<<gridG, 256>>>(a_hi, a_lo, wih_hi, wih_lo, b_ih, gi, Nn, G3H);
        gru_k<<<(Nn * Hh + 255) / 256, 256>>>(gi, gh, h, h_hi, h_lo);
    }

    // ELU + BN
    zero_f<<<2, 256>>>(colsum, Hh);
    zero_f<<<2, 256>>>(colsq, Hh);
    elu_stats_k<<<120, 256>>>(h, h2, colsum, colsq);
    bn_final_k<<<1, 256>>>(colsum, colsq, bn_g, bn_b, scale, shift);
    bn_apply_k<<<(Nn * Hh + 255) / 256, 256>>>(h2, scale, shift);

    // gate + pooling
    gate_k<<<(Nn + 7) / 8, 256>>>(h2, gate_w, gate_b, gate);
    zero_i<<<1, 64>>>(gcnt, Gg);
    ghist_k<<<(Nn + 255) / 256, 256>>>(n2g, gcnt);
    gscan_k<<<1, 32>>>(gcnt, gstart);
    pool_k<<<Gg, 256>>>(h2, gate, gstart, alpha, hg);

    // classifier
    mlp_k<<<Gg, 128>>>(hg, W1, b1, W2, b2, out);
}